// round 3
// baseline (speedup 1.0000x reference)
#include <cuda_runtime.h>

#define Hdim 256
#define Wdim 256
#define Cdim 64
#define UN   8
#define TR   32
#define PITCH 257
#define HSMEM (2 * TR * PITCH * 4)   // two in-place tiles: 65792 B

// ---------------------------------------------------------------------------
// Fused kernel. blockDim = 128.
//   bid % 9 == 8  -> vert block  (vid = bid/9, 256 blocks: one (b,c) slab,
//                    float2 per thread: 2 down-chains + 2 up-chains)
//   else          -> horiz block (hid = bid - bid/9, 2048 blocks: 32x256 tile,
//                    warp0 scans right in-place on tile A, warp1 left on B)
// ---------------------------------------------------------------------------
__global__ __launch_bounds__(128) void irnn_fused_kernel(
    const float* __restrict__ x,
    const float* __restrict__ w_up,    const float* __restrict__ b_up,
    const float* __restrict__ w_right, const float* __restrict__ b_right,
    const float* __restrict__ w_down,  const float* __restrict__ b_down,
    const float* __restrict__ w_left,  const float* __restrict__ b_left,
    float* __restrict__ out_up,   float* __restrict__ out_right,
    float* __restrict__ out_down, float* __restrict__ out_left)
{
    extern __shared__ float sm[];
    int bid = blockIdx.x;
    int tid = threadIdx.x;

    if (bid % 9 == 8) {
        // ================= VERTICAL (down forward, up backward) ============
        int bc = bid / 9;                 // (b*C + c) in [0,256)
        int c  = bc & (Cdim - 1);
        size_t off = (size_t)bc * (Hdim * Wdim) + 2 * tid;

        const float2* xp = (const float2*)(x        + off);
        float2*       od = (float2*)      (out_down + off);
        float2*       ou = (float2*)      (out_up   + off);
        const int RS = Wdim / 2;          // row stride in float2

        float wd = w_down[c], bd = b_down[c];
        float wu = w_up[c],   bu = b_up[c];

        float2 hd, hu;
        {   // peeled first chunk: h_0 = relu(x_0) at both ends
            float2 xf[UN], xb[UN];
            #pragma unroll
            for (int j = 0; j < UN; j++) {
                xf[j] = xp[j * RS];
                xb[j] = xp[(Hdim - 1 - j) * RS];
            }
            hd.x = fmaxf(xf[0].x, 0.f); hd.y = fmaxf(xf[0].y, 0.f);
            od[0] = hd;
            hu.x = fmaxf(xb[0].x, 0.f); hu.y = fmaxf(xb[0].y, 0.f);
            ou[(Hdim - 1) * RS] = hu;
            #pragma unroll
            for (int j = 1; j < UN; j++) {
                hd.x = fmaxf(fmaf(wd, hd.x, bd + xf[j].x), 0.f);
                hd.y = fmaxf(fmaf(wd, hd.y, bd + xf[j].y), 0.f);
                od[j * RS] = hd;
                hu.x = fmaxf(fmaf(wu, hu.x, bu + xb[j].x), 0.f);
                hu.y = fmaxf(fmaf(wu, hu.y, bu + xb[j].y), 0.f);
                ou[(Hdim - 1 - j) * RS] = hu;
            }
        }
        for (int t0 = UN; t0 < Hdim; t0 += UN) {
            float2 sf[UN], sb[UN];
            #pragma unroll
            for (int j = 0; j < UN; j++) {       // batched loads, bias folded
                float2 a = xp[(t0 + j) * RS];
                float2 b = xp[(Hdim - 1 - t0 - j) * RS];
                sf[j].x = bd + a.x; sf[j].y = bd + a.y;
                sb[j].x = bu + b.x; sb[j].y = bu + b.y;
            }
            #pragma unroll
            for (int j = 0; j < UN; j++) {
                hd.x = fmaxf(fmaf(wd, hd.x, sf[j].x), 0.f);
                hd.y = fmaxf(fmaf(wd, hd.y, sf[j].y), 0.f);
                od[(t0 + j) * RS] = hd;
                hu.x = fmaxf(fmaf(wu, hu.x, sb[j].x), 0.f);
                hu.y = fmaxf(fmaf(wu, hu.y, sb[j].y), 0.f);
                ou[(Hdim - 1 - t0 - j) * RS] = hu;
            }
        }
    } else {
        // ================= HORIZONTAL (right forward, left backward) =======
        int hid = bid - bid / 9;          // [0, 2048)
        float* A = sm;                    // tile copy for right scan (in place)
        float* B = sm + TR * PITCH;       // tile copy for left scan  (in place)

        int bc = hid >> 3;                // (b*C + c)
        int ht = hid & 7;                 // 32-row tile index within H
        int c  = bc & (Cdim - 1);

        size_t goff = (size_t)bc * (Hdim * Wdim) + (size_t)ht * (TR * Wdim);
        const float4* xp4 = (const float4*)(x + goff);

        // coalesced float4 tile load -> both smem copies
        for (int i = tid; i < TR * (Wdim / 4); i += 128) {
            int r   = i >> 6;
            int cw4 = (i & 63) << 2;
            float4 v = xp4[i];
            int base = r * PITCH + cw4;
            A[base] = v.x; A[base+1] = v.y; A[base+2] = v.z; A[base+3] = v.w;
            B[base] = v.x; B[base+1] = v.y; B[base+2] = v.z; B[base+3] = v.w;
        }
        __syncthreads();

        int warp = tid >> 5, lane = tid & 31;
        if (warp == 0) {                  // RIGHT scan, in place on A
            float wr = w_right[c], br = b_right[c];
            float* xr = A + lane * PITCH;
            float h;
            {
                float xv[UN];
                #pragma unroll
                for (int j = 0; j < UN; j++) xv[j] = xr[j];
                h = fmaxf(xv[0], 0.f); xr[0] = h;
                #pragma unroll
                for (int j = 1; j < UN; j++) {
                    h = fmaxf(fmaf(wr, h, br + xv[j]), 0.f); xr[j] = h;
                }
            }
            for (int t0 = UN; t0 < Wdim; t0 += UN) {
                float sv[UN];
                #pragma unroll
                for (int j = 0; j < UN; j++) sv[j] = br + xr[t0 + j];
                #pragma unroll
                for (int j = 0; j < UN; j++) {
                    h = fmaxf(fmaf(wr, h, sv[j]), 0.f); xr[t0 + j] = h;
                }
            }
        } else if (warp == 1) {           // LEFT scan, in place on B
            float wl = w_left[c], bl = b_left[c];
            float* xr = B + lane * PITCH;
            float h;
            {
                float xv[UN];
                #pragma unroll
                for (int j = 0; j < UN; j++) xv[j] = xr[Wdim - 1 - j];
                h = fmaxf(xv[0], 0.f); xr[Wdim - 1] = h;
                #pragma unroll
                for (int j = 1; j < UN; j++) {
                    h = fmaxf(fmaf(wl, h, bl + xv[j]), 0.f); xr[Wdim - 1 - j] = h;
                }
            }
            for (int t0 = UN; t0 < Wdim; t0 += UN) {
                float sv[UN];
                #pragma unroll
                for (int j = 0; j < UN; j++) sv[j] = bl + xr[Wdim - 1 - t0 - j];
                #pragma unroll
                for (int j = 0; j < UN; j++) {
                    h = fmaxf(fmaf(wl, h, sv[j]), 0.f); xr[Wdim - 1 - t0 - j] = h;
                }
            }
        }
        __syncthreads();

        // coalesced scalar stores (conflict-free smem reads)
        float* orp = out_right + goff;
        float* olp = out_left  + goff;
        for (int i = tid; i < TR * Wdim; i += 128) {
            int r = i >> 8, cw = i & 255;
            orp[i] = A[r * PITCH + cw];
            olp[i] = B[r * PITCH + cw];
        }
    }
}

// ---------------------------------------------------------------------------
// Launch. Output order: (up, right, down, left), each B*C*H*W floats.
// ---------------------------------------------------------------------------
extern "C" void kernel_launch(void* const* d_in, const int* in_sizes, int n_in,
                              void* d_out, int out_size)
{
    const float* x       = (const float*)d_in[0];
    const float* w_up    = (const float*)d_in[1];
    const float* b_up    = (const float*)d_in[2];
    const float* w_right = (const float*)d_in[3];
    const float* b_right = (const float*)d_in[4];
    const float* w_down  = (const float*)d_in[5];
    const float* b_down  = (const float*)d_in[6];
    const float* w_left  = (const float*)d_in[7];
    const float* b_left  = (const float*)d_in[8];
    float* out = (float*)d_out;

    const size_t N = (size_t)4 * Cdim * Hdim * Wdim; // 16,777,216

    static int smem_ok = -1;
    if (smem_ok < 0) {
        smem_ok = (cudaFuncSetAttribute(irnn_fused_kernel,
                     cudaFuncAttributeMaxDynamicSharedMemorySize, HSMEM)
                   == cudaSuccess) ? 1 : 0;
    }

    // 2048 horiz blocks + 256 vert blocks, interleaved (every 9th is vert)
    irnn_fused_kernel<<<2304, 128, HSMEM>>>(
        x, w_up, b_up, w_right, b_right, w_down, b_down, w_left, b_left,
        out /*up*/, out + N /*right*/, out + 2*N /*down*/, out + 3*N /*left*/);
}

// round 4
// speedup vs baseline: 1.4660x; 1.4660x over previous
#include <cuda_runtime.h>

#define Hdim 256
#define Wdim 256
#define Cdim 64
#define TR   32
#define PITCH 257
#define HSMEM (2 * TR * PITCH * 4)   // tile A (right) + tile B (left): 65792 B

__device__ __forceinline__ float relu_(float v) { return fmaxf(v, 0.f); }

// ---------------------------------------------------------------------------
// Vertical chunk scan over global memory (float2 column, row stride 128).
// WARM=false: 128 output rows starting at `start`.
// WARM=true : 32 warmup rows (cold start) then 128 output rows.
// ---------------------------------------------------------------------------
template<bool WARM>
__device__ __forceinline__ void vchunk(const float2* __restrict__ xcol,
                                       float2* __restrict__ ocol,
                                       float w, float b, int start, int step)
{
    const int RS = Wdim / 2;
    float2 h, xb[8];
    int r = start;
    #pragma unroll
    for (int j = 0; j < 8; j++) xb[j] = xcol[(r + j * step) * RS];
    h.x = relu_(xb[0].x); h.y = relu_(xb[0].y);
    if (!WARM) ocol[r * RS] = h;
    #pragma unroll
    for (int j = 1; j < 8; j++) {
        h.x = relu_(fmaf(w, h.x, b + xb[j].x));
        h.y = relu_(fmaf(w, h.y, b + xb[j].y));
        if (!WARM) ocol[(r + j * step) * RS] = h;
    }
    r += 8 * step;
    if (WARM) {
        #pragma unroll
        for (int t = 0; t < 3; t++) {   // 24 more warmup recurrences
            #pragma unroll
            for (int j = 0; j < 8; j++) xb[j] = xcol[(r + j * step) * RS];
            #pragma unroll
            for (int j = 0; j < 8; j++) {
                h.x = relu_(fmaf(w, h.x, b + xb[j].x));
                h.y = relu_(fmaf(w, h.y, b + xb[j].y));
            }
            r += 8 * step;
        }
    }
    const int NB = WARM ? 16 : 15;      // remaining output batches
    #pragma unroll 1
    for (int t = 0; t < NB; t++) {
        #pragma unroll
        for (int j = 0; j < 8; j++) xb[j] = xcol[(r + j * step) * RS];
        #pragma unroll
        for (int j = 0; j < 8; j++) {
            h.x = relu_(fmaf(w, h.x, b + xb[j].x));
            h.y = relu_(fmaf(w, h.y, b + xb[j].y));
            ocol[(r + j * step) * RS] = h;
        }
        r += 8 * step;
    }
}

// ---------------------------------------------------------------------------
// Fused kernel, blockDim = 256.
//   bid % 9 == 8 -> vert block: slab v=bid/9; half (tid>>7) = H-chunk 0/1;
//                   down + up chunked scans, float2 per thread.
//   else         -> horiz block: 32x256 tile; 8 warps = 4 chunks x 2 dirs,
//                   warmup-then-write phase split, in-place smem scan.
// ---------------------------------------------------------------------------
__global__ __launch_bounds__(256, 3) void irnn_fused_kernel(
    const float* __restrict__ x,
    const float* __restrict__ w_up,    const float* __restrict__ b_up,
    const float* __restrict__ w_right, const float* __restrict__ b_right,
    const float* __restrict__ w_down,  const float* __restrict__ b_down,
    const float* __restrict__ w_left,  const float* __restrict__ b_left,
    float* __restrict__ out_up,   float* __restrict__ out_right,
    float* __restrict__ out_down, float* __restrict__ out_left)
{
    extern __shared__ float sm[];
    int bid = blockIdx.x;
    int tid = threadIdx.x;

    if (bid % 9 == 8) {
        // ============================ VERTICAL ============================
        int bc   = bid / 9;            // slab (b*C + c) in [0,256)
        int k    = tid >> 7;           // H-chunk 0/1
        int lane = tid & 127;          // float2 column
        int c    = bc & (Cdim - 1);
        size_t base = (size_t)bc * (Hdim * Wdim);

        const float2* xcol = (const float2*)(x        + base) + lane;
        float2*       odc  = (float2*)      (out_down + base) + lane;
        float2*       ouc  = (float2*)      (out_up   + base) + lane;

        float wd = w_down[c], bd = b_down[c];
        float wu = w_up[c],   bu = b_up[c];

        if (k == 0) {
            vchunk<false>(xcol, odc, wd, bd, 0,   +1);  // down rows 0..127
            vchunk<false>(xcol, ouc, wu, bu, 255, -1);  // up   rows 255..128
        } else {
            vchunk<true >(xcol, odc, wd, bd, 96,  +1);  // warm 96..127 -> 128..255
            vchunk<true >(xcol, ouc, wu, bu, 159, -1);  // warm 159..128 -> 127..0
        }
    } else {
        // =========================== HORIZONTAL ===========================
        int hid = bid - bid / 9;       // [0, 2048)
        float* A = sm;                 // right-scan tile (in place)
        float* B = sm + TR * PITCH;    // left-scan tile  (in place)

        int bc = hid >> 3;
        int ht = hid & 7;
        int c  = bc & (Cdim - 1);
        size_t goff = (size_t)bc * (Hdim * Wdim) + (size_t)ht * (TR * Wdim);
        const float* xp = x + goff;

        // load: coalesced scalar LDG, conflict-free STS into both tiles
        #pragma unroll 4
        for (int i = tid; i < TR * Wdim; i += 256) {
            int r = i >> 8, cw = i & 255;
            float v = xp[i];
            int s = r * PITCH + cw;
            A[s] = v; B[s] = v;
        }
        __syncthreads();

        int warp = tid >> 5, lanr = tid & 31;  // lanr = row
        int cc  = warp >> 1;                    // chunk 0..3
        int dir = warp & 1;                     // 0=right(A), 1=left(B)
        // ptr[pos*s] addresses original position: right pos=t, left pos=255-t
        float* ptr = dir ? (B + lanr * PITCH + (Wdim - 1)) : (A + lanr * PITCH);
        int   sgn  = dir ? -1 : 1;
        float wv   = dir ? w_left[c] : w_right[c];
        float bv   = dir ? b_left[c] : b_right[c];

        // phase W: warmup (reads only, sees original x everywhere)
        float h = 0.f;
        if (cc > 0) {
            int p = cc * 64 - 32;
            float xv[8];
            #pragma unroll
            for (int j = 0; j < 8; j++) xv[j] = ptr[(p + j) * sgn];
            h = relu_(xv[0]);
            #pragma unroll
            for (int j = 1; j < 8; j++) h = relu_(fmaf(wv, h, bv + xv[j]));
            p += 8;
            #pragma unroll
            for (int t = 0; t < 3; t++) {
                #pragma unroll
                for (int j = 0; j < 8; j++) xv[j] = ptr[(p + j) * sgn];
                #pragma unroll
                for (int j = 0; j < 8; j++) h = relu_(fmaf(wv, h, bv + xv[j]));
                p += 8;
            }
        }
        __syncthreads();   // all warmup reads done before any in-place writes

        // phase S: write 64 positions in place (each warp owns its region)
        {
            int p = cc * 64;
            int t0 = 0;
            if (cc == 0) {
                float xv[8];
                #pragma unroll
                for (int j = 0; j < 8; j++) xv[j] = ptr[j * sgn];
                h = relu_(xv[0]); ptr[0] = h;
                #pragma unroll
                for (int j = 1; j < 8; j++) {
                    h = relu_(fmaf(wv, h, bv + xv[j])); ptr[j * sgn] = h;
                }
                p = 8; t0 = 1;
            }
            #pragma unroll 1
            for (int t = t0; t < 8; t++) {
                float xv[8];
                #pragma unroll
                for (int j = 0; j < 8; j++) xv[j] = ptr[(p + j) * sgn];
                #pragma unroll
                for (int j = 0; j < 8; j++) {
                    h = relu_(fmaf(wv, h, bv + xv[j])); ptr[(p + j) * sgn] = h;
                }
                p += 8;
            }
        }
        __syncthreads();

        // store: conflict-free LDS, coalesced STG
        float* orp = out_right + goff;
        float* olp = out_left  + goff;
        #pragma unroll 4
        for (int i = tid; i < TR * Wdim; i += 256) {
            int r = i >> 8, cw = i & 255;
            int s = r * PITCH + cw;
            orp[i] = A[s];
            olp[i] = B[s];
        }
    }
}

// ---------------------------------------------------------------------------
// Launch. Output order: (up, right, down, left), each B*C*H*W floats.
// ---------------------------------------------------------------------------
extern "C" void kernel_launch(void* const* d_in, const int* in_sizes, int n_in,
                              void* d_out, int out_size)
{
    const float* x       = (const float*)d_in[0];
    const float* w_up    = (const float*)d_in[1];
    const float* b_up    = (const float*)d_in[2];
    const float* w_right = (const float*)d_in[3];
    const float* b_right = (const float*)d_in[4];
    const float* w_down  = (const float*)d_in[5];
    const float* b_down  = (const float*)d_in[6];
    const float* w_left  = (const float*)d_in[7];
    const float* b_left  = (const float*)d_in[8];
    float* out = (float*)d_out;

    const size_t N = (size_t)4 * Cdim * Hdim * Wdim; // 16,777,216

    static int smem_ok = -1;
    if (smem_ok < 0) {
        smem_ok = (cudaFuncSetAttribute(irnn_fused_kernel,
                     cudaFuncAttributeMaxDynamicSharedMemorySize, HSMEM)
                   == cudaSuccess) ? 1 : 0;
    }

    // 2048 horiz blocks + 256 vert blocks (every 9th), blockDim 256
    irnn_fused_kernel<<<2304, 256, HSMEM>>>(
        x, w_up, b_up, w_right, b_right, w_down, b_down, w_left, b_left,
        out /*up*/, out + N /*right*/, out + 2*N /*down*/, out + 3*N /*left*/);
}